// round 2
// baseline (speedup 1.0000x reference)
#include <cuda_runtime.h>
#include <cstdint>

// ============================================================================
// StagePolicyNetwork: gather -> [208x128] tf32 mma.sync GEMM -> relu
// -> [128x64] GEMM -> relu -> [64x1] dot.  Persistent CTAs, compute_103-safe
// (no tcgen05: harness PTX target is sm_103 without 'a').
// ============================================================================

__device__ __forceinline__ uint32_t smem_u32(const void* p) {
    uint32_t a;
    asm("{ .reg .u64 t; cvta.to.shared.u64 t, %1; cvt.u32.u64 %0, t; }" : "=r"(a) : "l"(p));
    return a;
}
__device__ __forceinline__ uint32_t f2tf(float f) {
    uint32_t u; asm("cvt.rna.tf32.f32 %0, %1;" : "=r"(u) : "f"(f)); return u;
}
__device__ __forceinline__ void cp16(uint32_t saddr, const void* gaddr) {
    asm volatile("cp.async.cg.shared.global [%0], [%1], 16;" :: "r"(saddr), "l"(gaddr));
}
__device__ __forceinline__ void cp_commit() {
    asm volatile("cp.async.commit_group;" ::: "memory");
}
__device__ __forceinline__ void mma_tf32(float& c0, float& c1, float& c2, float& c3,
                                         uint32_t a0, uint32_t a1, uint32_t a2, uint32_t a3,
                                         uint32_t b0, uint32_t b1) {
    asm volatile(
        "mma.sync.aligned.m16n8k8.row.col.f32.tf32.tf32.f32 "
        "{%0,%1,%2,%3}, {%4,%5,%6,%7}, {%8,%9}, {%0,%1,%2,%3};"
        : "+f"(c0), "+f"(c1), "+f"(c2), "+f"(c3)
        : "r"(a0), "r"(a1), "r"(a2), "r"(a3), "r"(b0), "r"(b1));
}

// ---------------- constants --------------------------------------------------
static constexpr int TILE = 128;
static constexpr int KK1 = 26;          // 208 / 8
static constexpr int KK2 = 16;          // 128 / 8
static constexpr int NCHUNK = 13;       // 26 kk in chunks of 2

// SMEM layout (bytes)
static constexpr int SM_W1F  = 0;                      // 26*16*32*8 = 106496
static constexpr int SM_W2F  = 106496;                 // 16*8*32*8  = 32768
static constexpr int SM_AB   = 139264;                 // 2 bufs * 8192 = 16384
static constexpr int SM_H    = 155648;                 // 16*8*4*32*4 = 65536
static constexpr int SM_B1   = 221184;                 // 512
static constexpr int SM_B2   = 221696;                 // 256
static constexpr int SM_W3   = 221952;                 // 256
static constexpr int SM_PART = 222208;                 // 128*4*4 = 2048
static constexpr int SM_CUM  = 224256;                 // 80
static constexpr int SMEM_TOTAL = 224384;

__global__ __launch_bounds__(256, 1)
void stage_policy_kernel(
    const float* __restrict__ x, const float* __restrict__ hn,
    const float* __restrict__ hd, const float* __restrict__ hg,
    const float* __restrict__ W1g, const float* __restrict__ b1g,
    const float* __restrict__ W2g, const float* __restrict__ b2g,
    const float* __restrict__ W3g, const float* __restrict__ b3g,
    const int* __restrict__ stage_idx, const int* __restrict__ batch,
    const int* __restrict__ nsa,
    float* __restrict__ out, int M, int G, int ntiles)
{
    extern __shared__ char smem[];
    const uint32_t sb = smem_u32(smem);
    const int tid  = threadIdx.x;
    const int wid  = tid >> 5;
    const int lane = tid & 31;
    const int g4   = lane >> 2;     // groupID
    const int t4   = lane & 3;      // threadID_in_group
    const int mg   = wid >> 2;      // m-group: rows 64*mg .. +64
    const int ng   = wid & 3;       // n-group: layer1 cols 32*ng, layer2 cols 16*ng

    float* sB1  = (float*)(smem + SM_B1);
    float* sB2  = (float*)(smem + SM_B2);
    float* sW3  = (float*)(smem + SM_W3);
    float* sPt  = (float*)(smem + SM_PART);
    int*   sCum = (int*)(smem + SM_CUM);

    // ---------------- one-time fills ----------------
    // W1 fragment-major: [kk(26)][n(16)][lane(32)] x {b0,b1}
    for (int i = tid; i < KK1 * 16 * 32; i += 256) {
        int l = i & 31, n = (i >> 5) & 15, kk = i >> 9;
        int k0 = kk * 8 + (l & 3), col = n * 8 + (l >> 2);
        uint2 v;
        v.x = f2tf(W1g[k0 * 128 + col]);
        v.y = f2tf(W1g[(k0 + 4) * 128 + col]);
        ((uint2*)(smem + SM_W1F))[i] = v;
    }
    // W2 fragment-major: [kk(16)][n(8)][lane(32)] x {b0,b1}
    for (int i = tid; i < KK2 * 8 * 32; i += 256) {
        int l = i & 31, n = (i >> 5) & 7, kk = i >> 8;
        int k0 = kk * 8 + (l & 3), col = n * 8 + (l >> 2);
        uint2 v;
        v.x = f2tf(W2g[k0 * 64 + col]);
        v.y = f2tf(W2g[(k0 + 4) * 64 + col]);
        ((uint2*)(smem + SM_W2F))[i] = v;
    }
    if (tid < 128) sB1[tid] = b1g[tid];
    if (tid >= 128 && tid < 192) sB2[tid - 128] = b2g[tid - 128];
    if (tid >= 192) sW3[tid - 192] = W3g[tid - 192];
    if (tid == 0) {
        int c = 0; sCum[0] = 0;
        for (int i = 0; i < G; i++) { c += nsa[i]; sCum[i + 1] = c; }
    }
    const float b3v = b3g[0];
    __syncthreads();

    // gather role: thread handles row = tid>>1, columns half = tid&1
    const int grow = tid >> 1;
    const int half = tid & 1;

    for (int tile = blockIdx.x; tile < ntiles; tile += gridDim.x) {
        // ---- per-tile row pointers ----
        const int gr  = tile * TILE + grow;
        const int grc = (gr < M) ? gr : (M - 1);
        const int idx = stage_idx[grc];
        const int bd  = batch[idx];
        int gg = 0;
        #pragma unroll 1
        while (gg + 1 < G && grc >= sCum[gg + 1]) gg++;
        const float* px  = x  + (size_t)idx * 16;
        const float* phn = hn + (size_t)idx * 64;
        const float* phd = hd + (size_t)bd  * 64;
        const float* phg = hg + (size_t)gg  * 64;

        const int rlo = grow & 15, m2r = grow >> 4;
        // dest base within a chunk buffer for this thread (reg part 0)
        const uint32_t dbase = sb + SM_AB + (uint32_t)(half * 8 + m2r) * 512u
                               + (uint32_t)(rlo >> 3) * 128u + (uint32_t)(rlo & 7) * 16u;

        // issue one 16-col chunk c (2 kk) : this thread copies cols
        // [16c+8*half, +8) as two 16B cp.asyncs
        auto issue = [&](int c) {
            const int col0 = 16 * c + 8 * half;
            const float* p;
            if      (col0 < 16)  p = px  + col0;
            else if (col0 < 80)  p = phn + (col0 - 16);
            else if (col0 < 144) p = phd + (col0 - 80);
            else                 p = phg + (col0 - 144);
            const uint32_t d = dbase + (uint32_t)(c & 1) * 8192u;
            cp16(d,        p);        // klo 0..3  -> reg (rlo>>3)
            cp16(d + 256u, p + 4);    // klo 4..7  -> reg (rlo>>3)+2
            cp_commit();
        };

        issue(0);
        issue(1);

        float acc[4][4][4];
        #pragma unroll
        for (int a = 0; a < 4; a++)
            #pragma unroll
            for (int b = 0; b < 4; b++)
                #pragma unroll
                for (int q = 0; q < 4; q++) acc[a][b][q] = 0.f;

        // ---------------- layer 1 main loop ----------------
        #pragma unroll 1
        for (int c = 0; c < NCHUNK; c++) {
            if (c < NCHUNK - 1) asm volatile("cp.async.wait_group 1;" ::: "memory");
            else                asm volatile("cp.async.wait_group 0;" ::: "memory");
            __syncthreads();

            const char* ab = smem + SM_AB + (c & 1) * 8192;
            #pragma unroll
            for (int kkb = 0; kkb < 2; kkb++) {
                const int kk = 2 * c + kkb;
                uint32_t a[4][4];
                #pragma unroll
                for (int ml = 0; ml < 4; ml++) {
                    const uint32_t* ap =
                        (const uint32_t*)(ab + (kkb * 8 + 4 * mg + ml) * 512) + lane;
                    a[ml][0] = ap[0];  a[ml][1] = ap[32];
                    a[ml][2] = ap[64]; a[ml][3] = ap[96];
                }
                uint2 bf[4];
                #pragma unroll
                for (int nl = 0; nl < 4; nl++)
                    bf[nl] = ((const uint2*)(smem + SM_W1F))[(kk * 16 + 4 * ng + nl) * 32 + lane];
                #pragma unroll
                for (int ml = 0; ml < 4; ml++)
                    #pragma unroll
                    for (int nl = 0; nl < 4; nl++)
                        mma_tf32(acc[ml][nl][0], acc[ml][nl][1], acc[ml][nl][2], acc[ml][nl][3],
                                 a[ml][0], a[ml][1], a[ml][2], a[ml][3],
                                 bf[nl].x, bf[nl].y);
            }
            __syncthreads();
            if (c < NCHUNK - 2) issue(c + 2);
        }

        // ---------------- epilogue 1: +b1, relu, tf32 -> H (fragment-major) ----
        #pragma unroll
        for (int ml = 0; ml < 4; ml++) {
            #pragma unroll
            for (int nl = 0; nl < 4; nl++) {
                const int col0 = 32 * ng + 8 * nl + 2 * t4;
                const float2 bb = *(const float2*)(sB1 + col0);
                uint2 lo, hi;
                lo.x = f2tf(fmaxf(acc[ml][nl][0] + bb.x, 0.f));
                lo.y = f2tf(fmaxf(acc[ml][nl][1] + bb.y, 0.f));
                hi.x = f2tf(fmaxf(acc[ml][nl][2] + bb.x, 0.f));
                hi.y = f2tf(fmaxf(acc[ml][nl][3] + bb.y, 0.f));
                const int kk2 = 4 * ng + nl;
                const int m2  = 4 * mg + ml;
                const int reg = 2 * (t4 >> 1);
                const int ln2 = g4 * 4 + 2 * (t4 & 1);
                char* hp = smem + SM_H + ((kk2 * 8 + m2) * 4 + reg) * 128 + ln2 * 4;
                *(uint2*)(hp)       = lo;   // rows g   (c0,c1)
                *(uint2*)(hp + 128) = hi;   // rows g+8 (c2,c3)
            }
        }
        __syncthreads();

        // ---------------- layer 2 ----------------
        #pragma unroll
        for (int ml = 0; ml < 4; ml++)
            #pragma unroll
            for (int nl = 0; nl < 2; nl++)
                #pragma unroll
                for (int q = 0; q < 4; q++) acc[ml][nl][q] = 0.f;

        #pragma unroll 2
        for (int kk = 0; kk < KK2; kk++) {
            uint32_t a[4][4];
            #pragma unroll
            for (int ml = 0; ml < 4; ml++) {
                const uint32_t* ap =
                    (const uint32_t*)(smem + SM_H + (kk * 8 + 4 * mg + ml) * 512) + lane;
                a[ml][0] = ap[0];  a[ml][1] = ap[32];
                a[ml][2] = ap[64]; a[ml][3] = ap[96];
            }
            uint2 bf[2];
            #pragma unroll
            for (int nl = 0; nl < 2; nl++)
                bf[nl] = ((const uint2*)(smem + SM_W2F))[(kk * 8 + 2 * ng + nl) * 32 + lane];
            #pragma unroll
            for (int ml = 0; ml < 4; ml++)
                #pragma unroll
                for (int nl = 0; nl < 2; nl++)
                    mma_tf32(acc[ml][nl][0], acc[ml][nl][1], acc[ml][nl][2], acc[ml][nl][3],
                             a[ml][0], a[ml][1], a[ml][2], a[ml][3],
                             bf[nl].x, bf[nl].y);
        }

        // ---------------- epilogue 2: +b2, relu, dot W3, reduce ----------------
        #pragma unroll
        for (int ml = 0; ml < 4; ml++) {
            float p0 = 0.f, p1 = 0.f;
            #pragma unroll
            for (int nl = 0; nl < 2; nl++) {
                const int col0 = 16 * ng + 8 * nl + 2 * t4;
                const float2 bb = *(const float2*)(sB2 + col0);
                const float2 ww = *(const float2*)(sW3 + col0);
                p0 += fmaxf(acc[ml][nl][0] + bb.x, 0.f) * ww.x
                    + fmaxf(acc[ml][nl][1] + bb.y, 0.f) * ww.y;
                p1 += fmaxf(acc[ml][nl][2] + bb.x, 0.f) * ww.x
                    + fmaxf(acc[ml][nl][3] + bb.y, 0.f) * ww.y;
            }
            p0 += __shfl_xor_sync(0xffffffffu, p0, 1);
            p0 += __shfl_xor_sync(0xffffffffu, p0, 2);
            p1 += __shfl_xor_sync(0xffffffffu, p1, 1);
            p1 += __shfl_xor_sync(0xffffffffu, p1, 2);
            if (t4 == 0) {
                const int r0 = 64 * mg + 16 * ml + g4;
                sPt[r0 * 4 + ng]       = p0;
                sPt[(r0 + 8) * 4 + ng] = p1;
            }
        }
        __syncthreads();

        if (tid < 128) {
            const float4 p = ((const float4*)sPt)[tid];
            const int go = tile * TILE + tid;
            if (go < M) out[go] = p.x + p.y + p.z + p.w + b3v;
        }
        __syncthreads();
    }
}

// ---------------------------------------------------------------------------
extern "C" void kernel_launch(void* const* d_in, const int* in_sizes, int n_in,
                              void* d_out, int out_size) {
    const float* x   = (const float*)d_in[0];
    const float* hn  = (const float*)d_in[1];
    const float* hd  = (const float*)d_in[2];
    const float* hg  = (const float*)d_in[3];
    const float* W1  = (const float*)d_in[4];
    const float* b1  = (const float*)d_in[5];
    const float* W2  = (const float*)d_in[6];
    const float* b2  = (const float*)d_in[7];
    const float* W3  = (const float*)d_in[8];
    const float* b3  = (const float*)d_in[9];
    const int* sidx  = (const int*)d_in[10];
    const int* batch = (const int*)d_in[11];
    const int* nsa   = (const int*)d_in[12];
    float* out = (float*)d_out;

    const int M = in_sizes[10];
    const int G = in_sizes[12];
    const int ntiles = (M + TILE - 1) / TILE;

    static int sms = 0;
    if (sms == 0) {
        cudaDeviceGetAttribute(&sms, cudaDevAttrMultiProcessorCount, 0);
        cudaFuncSetAttribute(stage_policy_kernel,
                             cudaFuncAttributeMaxDynamicSharedMemorySize, SMEM_TOTAL);
        if (sms <= 0) sms = 148;
    }
    const int grid = (ntiles < sms) ? ntiles : sms;

    stage_policy_kernel<<<grid, 256, SMEM_TOTAL>>>(
        x, hn, hd, hg, W1, b1, W2, b2, W3, b3, sidx, batch, nsa, out, M, G, ntiles);
}

// round 3
// speedup vs baseline: 1.0213x; 1.0213x over previous
#include <cuda_runtime.h>
#include <cstdint>

// ============================================================================
// StagePolicyNetwork: gather -> [208x128] tf32 mma.sync GEMM -> relu
// -> [128x64] GEMM -> relu -> [64x1] dot.  Persistent CTAs, 512 threads,
// 3-deep cp.async pipeline, A-buffers overlaid on H. compute_103-safe.
// ============================================================================

__device__ __forceinline__ uint32_t smem_u32(const void* p) {
    uint32_t a;
    asm("{ .reg .u64 t; cvta.to.shared.u64 t, %1; cvt.u32.u64 %0, t; }" : "=r"(a) : "l"(p));
    return a;
}
__device__ __forceinline__ uint32_t f2tf(float f) {
    uint32_t u; asm("cvt.rna.tf32.f32 %0, %1;" : "=r"(u) : "f"(f)); return u;
}
__device__ __forceinline__ void cp16(uint32_t saddr, const void* gaddr) {
    asm volatile("cp.async.cg.shared.global [%0], [%1], 16;" :: "r"(saddr), "l"(gaddr));
}
__device__ __forceinline__ void cp_commit() {
    asm volatile("cp.async.commit_group;" ::: "memory");
}
template <int N>
__device__ __forceinline__ void cp_wait() {
    asm volatile("cp.async.wait_group %0;" :: "n"(N) : "memory");
}
__device__ __forceinline__ void mma_tf32(float& c0, float& c1, float& c2, float& c3,
                                         uint32_t a0, uint32_t a1, uint32_t a2, uint32_t a3,
                                         uint32_t b0, uint32_t b1) {
    asm volatile(
        "mma.sync.aligned.m16n8k8.row.col.f32.tf32.tf32.f32 "
        "{%0,%1,%2,%3}, {%4,%5,%6,%7}, {%8,%9}, {%0,%1,%2,%3};"
        : "+f"(c0), "+f"(c1), "+f"(c2), "+f"(c3)
        : "r"(a0), "r"(a1), "r"(a2), "r"(a3), "r"(b0), "r"(b1));
}

// ---------------- constants --------------------------------------------------
static constexpr int TILE = 128;
static constexpr int KK1 = 26;          // 208 / 8
static constexpr int KK2 = 16;          // 128 / 8
static constexpr int NCH = 7;           // chunks of 32 cols (4 kk); last has 2 kk

// SMEM layout (bytes)
static constexpr int SM_W1F  = 0;                      // 26*16*32*8 = 106496
static constexpr int SM_W2F  = 106496;                 // 16*8*32*8  = 32768
static constexpr int SM_H    = 139264;                 // 64 KB (layer-2 A)
static constexpr int SM_AB   = SM_H;                   // overlay: 3 x 16384 = 49152
static constexpr int SM_B1   = 204800;                 // 512
static constexpr int SM_B2   = 205312;                 // 256
static constexpr int SM_W3   = 205568;                 // 256
static constexpr int SM_PART = 205824;                 // 128*4*4 = 2048
static constexpr int SM_CUM  = 207872;                 // 80
static constexpr int SMEM_TOTAL = 208000;

__global__ __launch_bounds__(512, 1)
void stage_policy_kernel(
    const float* __restrict__ x, const float* __restrict__ hn,
    const float* __restrict__ hd, const float* __restrict__ hg,
    const float* __restrict__ W1g, const float* __restrict__ b1g,
    const float* __restrict__ W2g, const float* __restrict__ b2g,
    const float* __restrict__ W3g, const float* __restrict__ b3g,
    const int* __restrict__ stage_idx, const int* __restrict__ batch,
    const int* __restrict__ nsa,
    float* __restrict__ out, int M, int G, int ntiles)
{
    extern __shared__ char smem[];
    const uint32_t sb = smem_u32(smem);
    const int tid  = threadIdx.x;
    const int wid  = tid >> 5;
    const int lane = tid & 31;
    const int g4   = lane >> 2;     // groupID (row within 8)
    const int t4   = lane & 3;      // thread in group (col pair)
    const int mg   = wid >> 2;      // m-group: rows 32*mg .. +32
    const int ng   = wid & 3;       // n-group: L1 cols 32*ng, L2 cols 16*ng

    float* sB1  = (float*)(smem + SM_B1);
    float* sB2  = (float*)(smem + SM_B2);
    float* sW3  = (float*)(smem + SM_W3);
    float* sPt  = (float*)(smem + SM_PART);
    int*   sCum = (int*)(smem + SM_CUM);

    // ---------------- one-time fills ----------------
    // W1 fragment-major: [kk(26)][n(16)][lane(32)] x {b0,b1}
    for (int i = tid; i < KK1 * 16 * 32; i += 512) {
        int l = i & 31, n = (i >> 5) & 15, kk = i >> 9;
        int k0 = kk * 8 + (l & 3), col = n * 8 + (l >> 2);
        uint2 v;
        v.x = f2tf(W1g[k0 * 128 + col]);
        v.y = f2tf(W1g[(k0 + 4) * 128 + col]);
        ((uint2*)(smem + SM_W1F))[i] = v;
    }
    // W2 fragment-major: [kk(16)][n(8)][lane(32)] x {b0,b1}
    for (int i = tid; i < KK2 * 8 * 32; i += 512) {
        int l = i & 31, n = (i >> 5) & 7, kk = i >> 8;
        int k0 = kk * 8 + (l & 3), col = n * 8 + (l >> 2);
        uint2 v;
        v.x = f2tf(W2g[k0 * 64 + col]);
        v.y = f2tf(W2g[(k0 + 4) * 64 + col]);
        ((uint2*)(smem + SM_W2F))[i] = v;
    }
    if (tid < 128) sB1[tid] = b1g[tid];
    if (tid >= 128 && tid < 192) sB2[tid - 128] = b2g[tid - 128];
    if (tid >= 192 && tid < 256) sW3[tid - 192] = W3g[tid - 192];
    if (tid == 0) {
        int c = 0; sCum[0] = 0;
        for (int i = 0; i < G; i++) { c += nsa[i]; sCum[i + 1] = c; }
    }
    const float b3v = b3g[0];
    __syncthreads();

    // gather role: 4 threads per row; grow = row, q = col-quarter (8 cols)
    const int grow = tid >> 2;
    const int q    = tid & 3;
    const int rlo  = grow & 15, m2r = grow >> 4;
    const uint32_t dbase0 = sb + SM_AB + (uint32_t)(q * 8 + m2r) * 512u
                            + (uint32_t)(rlo >> 3) * 128u + (uint32_t)(rlo & 7) * 16u;

    // loop-carried gather indices (prefetched one tile ahead)
    int cidx, cbd;
    {
        const int gr0 = blockIdx.x * TILE + grow;
        const int grc = (gr0 < M) ? gr0 : (M - 1);
        cidx = stage_idx[grc];
        cbd  = batch[cidx];
    }

    for (int tile = blockIdx.x; tile < ntiles; tile += gridDim.x) {
        const int gr  = tile * TILE + grow;
        const int grc = (gr < M) ? gr : (M - 1);
        int gg = 0;
        #pragma unroll 1
        while (gg + 1 < G && grc >= sCum[gg + 1]) gg++;
        const float* px  = x  + (size_t)cidx * 16;
        const float* phn = hn + (size_t)cidx * 64;
        const float* phd = hd + (size_t)cbd  * 64;
        const float* phg = hg + (size_t)gg   * 64;

        // issue one 32-col chunk c: this thread copies cols [32c+8q, +8)
        auto issue = [&](int c) {
            const int col0 = 32 * c + 8 * q;
            if (col0 < 208) {
                const float* p;
                if      (col0 < 16)  p = px  + col0;
                else if (col0 < 80)  p = phn + (col0 - 16);
                else if (col0 < 144) p = phd + (col0 - 80);
                else                 p = phg + (col0 - 144);
                const uint32_t d = dbase0 + (uint32_t)(c % 3) * 16384u;
                cp16(d,        p);        // k 0..3 of this kk
                cp16(d + 256u, p + 4);    // k 4..7
            }
            cp_commit();
        };

        issue(0); issue(1); issue(2);

        // prefetch next tile's stage index (latency hidden behind layer 1)
        int nidx;
        {
            const int tn  = tile + gridDim.x;
            const int grn0 = tn * TILE + grow;
            const int grn = (tn < ntiles) ? ((grn0 < M) ? grn0 : (M - 1)) : grc;
            nidx = stage_idx[grn];
        }

        float acc[2][4][4];
        #pragma unroll
        for (int a = 0; a < 2; a++)
            #pragma unroll
            for (int b = 0; b < 4; b++)
                #pragma unroll
                for (int w = 0; w < 4; w++) acc[a][b][w] = 0.f;

        // ---------------- layer 1 main loop (fully unrolled chunks) ----------
        #pragma unroll
        for (int c = 0; c < NCH; c++) {
            if      (c <= 4) cp_wait<2>();
            else if (c == 5) cp_wait<1>();
            else             cp_wait<0>();
            __syncthreads();

            const char* ab = smem + SM_AB + (c % 3) * 16384;
            const int kkmax = (c == NCH - 1) ? 2 : 4;
            #pragma unroll
            for (int kk = 0; kk < 4; kk++) {
                if (kk >= kkmax) break;
                uint32_t a[2][4];
                #pragma unroll
                for (int ml = 0; ml < 2; ml++) {
                    const uint32_t* ap =
                        (const uint32_t*)(ab + (kk * 8 + 2 * mg + ml) * 512) + lane;
                    a[ml][0] = ap[0];  a[ml][1] = ap[32];
                    a[ml][2] = ap[64]; a[ml][3] = ap[96];
                }
                const int kkg = 4 * c + kk;
                uint2 bf[4];
                #pragma unroll
                for (int nl = 0; nl < 4; nl++)
                    bf[nl] = ((const uint2*)(smem + SM_W1F))[(kkg * 16 + 4 * ng + nl) * 32 + lane];
                #pragma unroll
                for (int ml = 0; ml < 2; ml++)
                    #pragma unroll
                    for (int nl = 0; nl < 4; nl++)
                        mma_tf32(acc[ml][nl][0], acc[ml][nl][1], acc[ml][nl][2], acc[ml][nl][3],
                                 a[ml][0], a[ml][1], a[ml][2], a[ml][3],
                                 bf[nl].x, bf[nl].y);
            }
            __syncthreads();
            if (c + 3 < NCH) issue(c + 3);
        }

        // prefetch next tile's batch (needs nidx; hidden behind epilogues)
        const int nbd = batch[nidx];

        // ---------------- epilogue 1: +b1, relu, tf32 -> H (fragment-major) --
        #pragma unroll
        for (int ml = 0; ml < 2; ml++) {
            #pragma unroll
            for (int nl = 0; nl < 4; nl++) {
                const int col0 = 32 * ng + 8 * nl + 2 * t4;
                const float2 bb = *(const float2*)(sB1 + col0);
                uint2 lo, hi;
                lo.x = f2tf(fmaxf(acc[ml][nl][0] + bb.x, 0.f));
                lo.y = f2tf(fmaxf(acc[ml][nl][1] + bb.y, 0.f));
                hi.x = f2tf(fmaxf(acc[ml][nl][2] + bb.x, 0.f));
                hi.y = f2tf(fmaxf(acc[ml][nl][3] + bb.y, 0.f));
                const int kk2 = 4 * ng + nl;
                const int m2  = 2 * mg + ml;
                const int reg = 2 * (t4 >> 1);
                const int ln2 = g4 * 4 + 2 * (t4 & 1);
                char* hp = smem + SM_H + ((kk2 * 8 + m2) * 4 + reg) * 128 + ln2 * 4;
                *(uint2*)(hp)       = lo;   // rows g4    (c0,c1)
                *(uint2*)(hp + 128) = hi;   // rows g4+8  (c2,c3)
            }
        }
        __syncthreads();

        // ---------------- layer 2 ----------------
        float ac2[2][2][4];
        #pragma unroll
        for (int a = 0; a < 2; a++)
            #pragma unroll
            for (int b = 0; b < 2; b++)
                #pragma unroll
                for (int w = 0; w < 4; w++) ac2[a][b][w] = 0.f;

        #pragma unroll 4
        for (int kk = 0; kk < KK2; kk++) {
            uint32_t a[2][4];
            #pragma unroll
            for (int ml = 0; ml < 2; ml++) {
                const uint32_t* ap =
                    (const uint32_t*)(smem + SM_H + (kk * 8 + 2 * mg + ml) * 512) + lane;
                a[ml][0] = ap[0];  a[ml][1] = ap[32];
                a[ml][2] = ap[64]; a[ml][3] = ap[96];
            }
            uint2 bf[2];
            #pragma unroll
            for (int nl = 0; nl < 2; nl++)
                bf[nl] = ((const uint2*)(smem + SM_W2F))[(kk * 8 + 2 * ng + nl) * 32 + lane];
            #pragma unroll
            for (int ml = 0; ml < 2; ml++)
                #pragma unroll
                for (int nl = 0; nl < 2; nl++)
                    mma_tf32(ac2[ml][nl][0], ac2[ml][nl][1], ac2[ml][nl][2], ac2[ml][nl][3],
                             a[ml][0], a[ml][1], a[ml][2], a[ml][3],
                             bf[nl].x, bf[nl].y);
        }

        // ---------------- epilogue 2: +b2, relu, dot W3, reduce --------------
        #pragma unroll
        for (int ml = 0; ml < 2; ml++) {
            float p0 = 0.f, p1 = 0.f;
            #pragma unroll
            for (int nl = 0; nl < 2; nl++) {
                const int col0 = 16 * ng + 8 * nl + 2 * t4;
                const float2 bb = *(const float2*)(sB2 + col0);
                const float2 ww = *(const float2*)(sW3 + col0);
                p0 += fmaxf(ac2[ml][nl][0] + bb.x, 0.f) * ww.x
                    + fmaxf(ac2[ml][nl][1] + bb.y, 0.f) * ww.y;
                p1 += fmaxf(ac2[ml][nl][2] + bb.x, 0.f) * ww.x
                    + fmaxf(ac2[ml][nl][3] + bb.y, 0.f) * ww.y;
            }
            p0 += __shfl_xor_sync(0xffffffffu, p0, 1);
            p0 += __shfl_xor_sync(0xffffffffu, p0, 2);
            p1 += __shfl_xor_sync(0xffffffffu, p1, 1);
            p1 += __shfl_xor_sync(0xffffffffu, p1, 2);
            if (t4 == 0) {
                const int r0 = 32 * mg + 16 * ml + g4;
                sPt[r0 * 4 + ng]       = p0;
                sPt[(r0 + 8) * 4 + ng] = p1;
            }
        }
        __syncthreads();

        if (tid < 128) {
            const float4 p = ((const float4*)sPt)[tid];
            const int go = tile * TILE + tid;
            if (go < M) out[go] = p.x + p.y + p.z + p.w + b3v;
        }
        __syncthreads();

        cidx = nidx; cbd = nbd;
    }
}

// ---------------------------------------------------------------------------
extern "C" void kernel_launch(void* const* d_in, const int* in_sizes, int n_in,
                              void* d_out, int out_size) {
    const float* x   = (const float*)d_in[0];
    const float* hn  = (const float*)d_in[1];
    const float* hd  = (const float*)d_in[2];
    const float* hg  = (const float*)d_in[3];
    const float* W1  = (const float*)d_in[4];
    const float* b1  = (const float*)d_in[5];
    const float* W2  = (const float*)d_in[6];
    const float* b2  = (const float*)d_in[7];
    const float* W3  = (const float*)d_in[8];
    const float* b3  = (const float*)d_in[9];
    const int* sidx  = (const int*)d_in[10];
    const int* batch = (const int*)d_in[11];
    const int* nsa   = (const int*)d_in[12];
    float* out = (float*)d_out;

    const int M = in_sizes[10];
    const int G = in_sizes[12];
    const int ntiles = (M + TILE - 1) / TILE;

    static int sms = 0;
    if (sms == 0) {
        cudaDeviceGetAttribute(&sms, cudaDevAttrMultiProcessorCount, 0);
        cudaFuncSetAttribute(stage_policy_kernel,
                             cudaFuncAttributeMaxDynamicSharedMemorySize, SMEM_TOTAL);
        if (sms <= 0) sms = 148;
    }
    const int grid = (ntiles < sms) ? ntiles : sms;

    stage_policy_kernel<<<grid, 512, SMEM_TOTAL>>>(
        x, hn, hd, hg, W1, b1, W2, b2, W3, b3, sidx, batch, nsa, out, M, G, ntiles);
}